// round 1
// baseline (speedup 1.0000x reference)
#include <cuda_runtime.h>
#include <cstdint>

// ---------------- problem constants (fixed shapes) ----------------
#define NNODES 10000
#define NEDGES 80000
#define BF     48          // B*S = 4*12
#define DD     32
#define NH     4
#define NK     3
#define NHK    12          // H*K
#define NC     24          // 12 src scores + 12 dst scores
#define NROWS  (BF * NNODES)   // 480000
#define KDIM   (NHK * DD)      // 384

// ---------------- device scratch (static, allocation-free) ----------------
__device__ float g_S[(size_t)NROWS * NC];        // 46 MB  : per-row 24 scores
__device__ float g_AGG[(size_t)NROWS * KDIM];    // 737 MB : aggregated input-space features
__device__ float g_wv[NC * DD];                  // 24 x 32 projection vectors
__device__ int   g_counts[NNODES];
__device__ int   g_off[NNODES + 1];
__device__ int   g_fill[NNODES];
__device__ int   g_eid[NEDGES];

// ---------------- K1: wv[c][i] = sum_j W[h,k,i,j] * a_{src|dst}[h,j] ----------------
__global__ void k_wvec(const float* __restrict__ W,
                       const float* __restrict__ a_src,
                       const float* __restrict__ a_dst) {
    int t = threadIdx.x;
    if (t >= NC * DD) return;
    int c  = t >> 5;            // 0..23
    int i  = t & 31;
    int hk = (c < NHK) ? c : c - NHK;
    const float* av  = (c < NHK) ? (a_src + (hk / NK) * DD) : (a_dst + (hk / NK) * DD);
    const float* wr  = W + ((size_t)hk * DD + i) * DD;
    float s = 0.f;
#pragma unroll
    for (int j = 0; j < DD; j++) s = fmaf(wr[j], av[j], s);
    g_wv[c * DD + i] = s;
}

// ---------------- K2: S[row][c] = x[row] . wv[c]  (row = b*N+n) ----------------
__global__ void __launch_bounds__(256) k_scores(const float* __restrict__ x) {
    __shared__ float wv[NC * DD];
    for (int i = threadIdx.x; i < NC * DD; i += blockDim.x) wv[i] = g_wv[i];
    __syncthreads();
    int row = blockIdx.x * blockDim.x + threadIdx.x;
    if (row >= NROWS) return;
    const float4* xr = (const float4*)(x + (size_t)row * DD);
    float xv[DD];
#pragma unroll
    for (int q = 0; q < 8; q++) {
        float4 v = xr[q];
        xv[4 * q + 0] = v.x; xv[4 * q + 1] = v.y; xv[4 * q + 2] = v.z; xv[4 * q + 3] = v.w;
    }
    float* srow = g_S + (size_t)row * NC;
#pragma unroll
    for (int c = 0; c < NC; c++) {
        float s = 0.f;
#pragma unroll
        for (int i = 0; i < DD; i++) s = fmaf(xv[i], wv[c * DD + i], s);
        srow[c] = s;
    }
}

// ---------------- CSR build ----------------
__global__ void k_zero() {
    int t = blockIdx.x * blockDim.x + threadIdx.x;
    if (t < NNODES) { g_counts[t] = 0; g_fill[t] = 0; }
}
__global__ void k_hist(const int* __restrict__ dst) {
    int e = blockIdx.x * blockDim.x + threadIdx.x;
    if (e < NEDGES) atomicAdd(&g_counts[dst[e]], 1);
}
__global__ void k_scan() {   // 1 block, 1024 threads
    __shared__ int buf[1024];
    int tid = threadIdx.x;
    int carry = 0;
    for (int base = 0; base < NNODES; base += 1024) {
        int idx = base + tid;
        int v = (idx < NNODES) ? g_counts[idx] : 0;
        buf[tid] = v;
        __syncthreads();
        int incl = v;
#pragma unroll
        for (int d = 1; d < 1024; d <<= 1) {
            int t2 = (tid >= d) ? buf[tid - d] : 0;
            __syncthreads();
            incl += t2;
            buf[tid] = incl;
            __syncthreads();
        }
        if (idx < NNODES) g_off[idx] = carry + incl - v;
        carry += buf[1023];
        __syncthreads();
    }
    if (tid == 0) g_off[NNODES] = carry;
}
__global__ void k_scatter(const int* __restrict__ dst) {
    int e = blockIdx.x * blockDim.x + threadIdx.x;
    if (e < NEDGES) {
        int d = dst[e];
        int pos = g_off[d] + atomicAdd(&g_fill[d], 1);
        g_eid[pos] = e;
    }
}

// ---------------- K4: per (node, b-pair) warp: softmax + input-space aggregation ----
// lanes 0..23 own (hk = lane%12, b = b0 + lane/12) softmax state
// all 32 lanes own (b = b0 + lane/16, dims 2*(lane%16)..+1) AGG accumulators
__global__ void __launch_bounds__(256) k_attn_agg(const float* __restrict__ x,
                                                  const int*   __restrict__ src,
                                                  const float* __restrict__ sup) {
    int warp = (blockIdx.x * blockDim.x + threadIdx.x) >> 5;
    int lane = threadIdx.x & 31;
    if (warp >= NNODES * (BF / 2)) return;
    int n  = warp % NNODES;
    int bp = warp / NNODES;
    int b0 = bp * 2;
    int p0 = g_off[n], p1 = g_off[n + 1];

    // ---- pass A: online softmax (max & denom) per (hk, b) on lanes 0..23 ----
    int  hk   = lane % NHK;
    int  bA   = b0 + ((lane < NHK) ? 0 : 1);
    bool actA = lane < 2 * NHK;
    int  kk   = hk % NK;
    float m = -1e30f, den = 0.f, sd = 0.f;
    if (actA) sd = g_S[((size_t)bA * NNODES + n) * NC + NHK + hk];
    for (int p = p0; p < p1; p++) {
        int e = g_eid[p];
        int s = src[e];
        if (actA) {
            float l = g_S[((size_t)bA * NNODES + s) * NC + hk] + sd;
            l = (l > 0.f) ? l : 0.2f * l;
            float nm = fmaxf(m, l);
            den = den * __expf(m - nm) + __expf(l - nm);
            m = nm;
        }
    }
    float invden = 1.f / (den + 1e-9f);

    // ---- pass B: alpha * support_w weighted aggregation of x[src] ----
    int d0 = (lane & 15) * 2;
    int bB = b0 + (lane >> 4);
    const float* xb   = x + ((size_t)bB * NNODES) * DD + d0;
    int sbase = (lane >> 4) * NHK;          // shuffle source base: 0 or 12
    float2 agg[NHK];
#pragma unroll
    for (int j = 0; j < NHK; j++) agg[j] = make_float2(0.f, 0.f);

    for (int p = p0; p < p1; p++) {
        int e = g_eid[p];
        int s = src[e];
        float a = 0.f;
        if (actA) {
            float l = g_S[((size_t)bA * NNODES + s) * NC + hk] + sd;
            l = (l > 0.f) ? l : 0.2f * l;
            a = __expf(l - m) * invden * sup[kk * NEDGES + e];
        }
        float2 xv = *(const float2*)(xb + (size_t)s * DD);
#pragma unroll
        for (int j = 0; j < NHK; j++) {
            float aj = __shfl_sync(0xffffffffu, a, sbase + j);
            agg[j].x = fmaf(aj, xv.x, agg[j].x);
            agg[j].y = fmaf(aj, xv.y, agg[j].y);
        }
    }
    float* arow = g_AGG + ((size_t)bB * NNODES + n) * KDIM + d0;
#pragma unroll
    for (int j = 0; j < NHK; j++) __stcs((float2*)(arow + j * DD), agg[j]);
}

// ---------------- K5: out = relu( (AGG @ Wstack) / H + inputs ) ----------------
// M = 480000, K = 384, N = 32. W (49KB) resident in smem per block.
#define GM_ROWS 128
#define ASM_LD  36   // 16B-aligned padded lead dim
__global__ void __launch_bounds__(256) k_gemm(const float* __restrict__ W,
                                              const float* __restrict__ inp,
                                              float* __restrict__ out) {
    extern __shared__ float sm[];
    float* Wsm = sm;                    // 384*32
    float* Asm = sm + KDIM * DD;        // 128*36
    int tid = threadIdx.x;

    const float4* W4   = (const float4*)W;
    float4*       Wsm4 = (float4*)Wsm;
    for (int i = tid; i < (KDIM * DD) / 4; i += 256) Wsm4[i] = W4[i];

    size_t row0 = (size_t)blockIdx.x * GM_ROWS;
    int rq = tid >> 3;                  // 0..31
    int cq = tid & 7;                   // 0..7
    int r0 = rq * 4, c0 = cq * 4;
    float acc[4][4];
#pragma unroll
    for (int a = 0; a < 4; a++)
#pragma unroll
        for (int b = 0; b < 4; b++) acc[a][b] = 0.f;

    for (int kc = 0; kc < NHK; kc++) {
        __syncthreads();
        // stage 128 x 32 chunk of AGG (streaming loads)
        for (int i = tid; i < 1024; i += 256) {
            int row = i >> 3, q = i & 7;
            float4 v = __ldcs((const float4*)(g_AGG + (row0 + row) * KDIM + kc * 32 + q * 4));
            *(float4*)(Asm + row * ASM_LD + q * 4) = v;
        }
        __syncthreads();
#pragma unroll
        for (int k = 0; k < 32; k++) {
            float4 wv = *(const float4*)(Wsm + (kc * 32 + k) * DD + c0);
#pragma unroll
            for (int jr = 0; jr < 4; jr++) {
                float av = Asm[(r0 + jr) * ASM_LD + k];
                acc[jr][0] = fmaf(av, wv.x, acc[jr][0]);
                acc[jr][1] = fmaf(av, wv.y, acc[jr][1]);
                acc[jr][2] = fmaf(av, wv.z, acc[jr][2]);
                acc[jr][3] = fmaf(av, wv.w, acc[jr][3]);
            }
        }
    }
    // epilogue: /H, residual, relu
#pragma unroll
    for (int jr = 0; jr < 4; jr++) {
        size_t o = (row0 + r0 + jr) * DD + c0;
        float4 iv = *(const float4*)(inp + o);
        float4 r;
        r.x = fmaxf(fmaf(acc[jr][0], 0.25f, iv.x), 0.f);
        r.y = fmaxf(fmaf(acc[jr][1], 0.25f, iv.y), 0.f);
        r.z = fmaxf(fmaf(acc[jr][2], 0.25f, iv.z), 0.f);
        r.w = fmaxf(fmaf(acc[jr][3], 0.25f, iv.w), 0.f);
        *(float4*)(out + o) = r;
    }
}

// ---------------- launch ----------------
extern "C" void kernel_launch(void* const* d_in, const int* in_sizes, int n_in,
                              void* d_out, int out_size) {
    const float* x     = (const float*)d_in[0];   // [48,10000,32]
    const int*   src   = (const int*)  d_in[1];   // [E]
    const int*   dst   = (const int*)  d_in[2];   // [E]
    const float* sup   = (const float*)d_in[3];   // [3,E]
    const float* W     = (const float*)d_in[4];   // [4,3,32,32]
    const float* a_s   = (const float*)d_in[5];   // [4,32]
    const float* a_d   = (const float*)d_in[6];   // [4,32]
    float*       out   = (float*)d_out;

    k_wvec<<<1, NC * DD>>>(W, a_s, a_d);
    k_scores<<<(NROWS + 255) / 256, 256>>>(x);
    k_zero<<<(NNODES + 255) / 256, 256>>>();
    k_hist<<<(NEDGES + 255) / 256, 256>>>(dst);
    k_scan<<<1, 1024>>>();
    k_scatter<<<(NEDGES + 255) / 256, 256>>>(dst);
    k_attn_agg<<<(NNODES * (BF / 2) * 32 + 255) / 256, 256>>>(x, src, sup);

    int smem = (KDIM * DD + GM_ROWS * ASM_LD) * (int)sizeof(float);  // 67584
    cudaFuncSetAttribute(k_gemm, cudaFuncAttributeMaxDynamicSharedMemorySize, smem);
    k_gemm<<<NROWS / GM_ROWS, 256, smem>>>(W, x, out);
}